// round 14
// baseline (speedup 1.0000x reference)
#include <cuda_runtime.h>
#include <cuda_fp16.h>
#include <stdint.h>

// ---------------------------------------------------------------------------
// Linear attention (causal QK^T, NO softmax) via chunked prefix-state, with
// projections folded into G' = (Wq^T Wk / sqrt(H)) * 1024 and W2 = Wo Wv:
//   U' = Tn G' ; scores' = U' Tn^T ; Z' = tril(scores') Tn + U' Tpre
//   out = LN2(x + (0.1/1024) * Z' W2^T)
// T_c = Tn_c^T Tn_c, Tpre = exclusive prefix sum of T over chunks.
// NO grid barriers: per-chunk dataflow flags (tflag: T ready; prog: scan
// progress per walker-CTA, epoch-tagged for graph replay).  Phase C is
// reordered so all Tpre-independent MMAs run before the Tpre wait.
// 256 threads, m16 x n128 warp tiles, f16 accumulators, 2 CTAs/SM (all 256
// CTAs co-resident -> dataflow spin loops are deadlock-free).
// ---------------------------------------------------------------------------

#define NB      4
#define NSEQ    8192
#define CH      128
#define NCB     (NSEQ / CH)        // 64
#define NCHUNK  (NB * NCB)         // 256
#define TILE    16384              // 128*128
#define RSQRT_H 0.08838834764831845f
#define PRESCALE 1024.0f
#define FINAL_SCALE (0.1f / 1024.0f)

__device__ __half g_S [NCHUNK * TILE];   // per-chunk gram T_c
__device__ __half g_M [NCHUNK * TILE];   // exclusive prefix Tpre
__device__ __half g_G [TILE];            // (Wq^T Wk / sqrt(H)) * 1024
__device__ __half g_W2[TILE];            // Wo @ Wv

// dataflow state (zero-init; epoch grows monotonically across graph replays)
__device__ int g_epoch = 0;
__device__ int g_tflag[NCHUNK];          // == epoch when T_c is ready
__device__ int g_prog [NCHUNK];          // epoch*NCB + chunks_scanned (per walker-CTA)

// =========================== helpers =======================================
__device__ __forceinline__ uint32_t smem_u32(const void* p) {
    uint32_t a;
    asm("{ .reg .u64 t; cvta.to.shared.u64 t, %1; cvt.u32.u64 %0, t; }"
        : "=r"(a) : "l"(p));
    return a;
}

__device__ __forceinline__ uint32_t swz(int row, int colg) {
    return (uint32_t)(row * 256) + (uint32_t)(((colg ^ (row & 7)) << 4));
}

__device__ __forceinline__ uint32_t pack_h(float lo, float hi) {
    __half2 h = __floats2half2_rn(lo, hi);
    return *reinterpret_cast<uint32_t*>(&h);
}

__device__ __forceinline__ void ldm4(uint32_t addr, uint32_t r[4]) {
    asm volatile("ldmatrix.sync.aligned.m8n8.x4.shared.b16 {%0,%1,%2,%3}, [%4];"
                 : "=r"(r[0]), "=r"(r[1]), "=r"(r[2]), "=r"(r[3]) : "r"(addr));
}
__device__ __forceinline__ void ldm4t(uint32_t addr, uint32_t r[4]) {
    asm volatile("ldmatrix.sync.aligned.m8n8.x4.trans.shared.b16 {%0,%1,%2,%3}, [%4];"
                 : "=r"(r[0]), "=r"(r[1]), "=r"(r[2]), "=r"(r[3]) : "r"(addr));
}

__device__ __forceinline__ void mma_hf(float* c, const uint32_t a[4],
                                       uint32_t b0, uint32_t b1) {
    asm volatile(
        "mma.sync.aligned.m16n8k16.row.col.f32.f16.f16.f32 "
        "{%0,%1,%2,%3},{%4,%5,%6,%7},{%8,%9},{%0,%1,%2,%3};"
        : "+f"(c[0]), "+f"(c[1]), "+f"(c[2]), "+f"(c[3])
        : "r"(a[0]), "r"(a[1]), "r"(a[2]), "r"(a[3]), "r"(b0), "r"(b1));
}
__device__ __forceinline__ void mma_hh(uint32_t c[2], const uint32_t a[4],
                                       uint32_t b0, uint32_t b1) {
    asm volatile(
        "mma.sync.aligned.m16n8k16.row.col.f16.f16.f16.f16 "
        "{%0,%1},{%2,%3,%4,%5},{%6,%7},{%0,%1};"
        : "+r"(c[0]), "+r"(c[1])
        : "r"(a[0]), "r"(a[1]), "r"(a[2]), "r"(a[3]), "r"(b0), "r"(b1));
}

// cp.async 128x128 f16 gmem tile -> swizzled smem tile (256 threads)
__device__ __forceinline__ void cp_tile(uint32_t dst, const __half* __restrict__ src,
                                        int tid) {
#pragma unroll
    for (int i = 0; i < 8; i++) {
        int idx = tid + i * 256;
        int row = idx >> 4, g = idx & 15;
        asm volatile("cp.async.cg.shared.global [%0], [%1], 16;"
                     :: "r"(dst + swz(row, g)),
                        "l"((const void*)(((const uint4*)src) + idx)));
    }
}
#define CP_COMMIT() asm volatile("cp.async.commit_group;" ::: "memory")
#define CP_WAIT()   asm volatile("cp.async.wait_all;" ::: "memory")
#define CP_WAIT_G(n) asm volatile("cp.async.wait_group %0;" :: "n"(n) : "memory")

// fp32 row-major 128x128 gmem -> f16 swizzled smem tile (256 threads)
__device__ __forceinline__ void load_w(char* dst, const float* __restrict__ W, int tid) {
#pragma unroll
    for (int i = 0; i < 8; i++) {
        int idx = tid + i * 256;
        int row = idx >> 4, g = idx & 15;
        const float4* p = (const float4*)(W + row * 128 + g * 8);
        float4 v0 = p[0], v1 = p[1];
        uint4 o;
        o.x = pack_h(v0.x, v0.y);  o.y = pack_h(v0.z, v0.w);
        o.z = pack_h(v1.x, v1.y);  o.w = pack_h(v1.z, v1.w);
        *(uint4*)(dst + swz(row, g)) = o;
    }
}

// B-operand ldmatrix for n-half nh (8 n8-tiles), k-block kk.
template <int BTR>
__device__ __forceinline__ void ldB(uint32_t sb, int kk, int nh, int lane,
                                    uint32_t b[4][4]) {
#pragma unroll
    for (int q = 0; q < 4; q++) {
        int idx = nh * 4 + q;
        if (!BTR) {
            ldm4(sb + swz(idx * 16 + ((lane >> 4) << 3) + (lane & 7),
                          kk * 2 + ((lane >> 3) & 1)), b[q]);
        } else {
            ldm4t(sb + swz(kk * 16 + ((lane >> 3) & 1) * 8 + (lane & 7),
                           idx * 2 + (lane >> 4)), b[q]);
        }
    }
}

// m16 x n128 x k128, A from smem, f32 accum.
template <int ATR, int BTR>
__device__ __forceinline__ void mm_s32(uint32_t sa, uint32_t sb,
                                       float acc[16][4], int lane, int mo) {
#pragma unroll
    for (int kk = 0; kk < 8; kk++) {
        uint32_t a[4];
        if (!ATR) {
            ldm4(sa + swz(mo + (lane & 15), kk * 2 + (lane >> 4)), a);
        } else {
            ldm4t(sa + swz(kk * 16 + ((lane >> 4) << 3) + (lane & 7),
                           (mo >> 3) + ((lane >> 3) & 1)), a);
        }
#pragma unroll
        for (int nh = 0; nh < 2; nh++) {
            uint32_t b[4][4];
            ldB<BTR>(sb, kk, nh, lane, b);
#pragma unroll
            for (int j = 0; j < 8; j++)
                mma_hf(acc[nh * 8 + j], a,
                       b[j >> 1][(j & 1) * 2], b[j >> 1][(j & 1) * 2 + 1]);
        }
    }
}

// m16 x n128 x k128, A from smem (non-trans), f16 accum (accumulates).
template <int BTR>
__device__ __forceinline__ void mm_s16(uint32_t sa, uint32_t sb,
                                       uint32_t acc[16][2], int lane, int mo) {
#pragma unroll
    for (int kk = 0; kk < 8; kk++) {
        uint32_t a[4];
        ldm4(sa + swz(mo + (lane & 15), kk * 2 + (lane >> 4)), a);
#pragma unroll
        for (int nh = 0; nh < 2; nh++) {
            uint32_t b[4][4];
            ldB<BTR>(sb, kk, nh, lane, b);
#pragma unroll
            for (int j = 0; j < 8; j++)
                mma_hh(acc[nh * 8 + j], a,
                       b[j >> 1][(j & 1) * 2], b[j >> 1][(j & 1) * 2 + 1]);
        }
    }
}

// A = f16 C-frags (identity), B from smem, f16 accum (accumulates).
template <int BTR>
__device__ __forceinline__ void mm_fh(const uint32_t U[16][2], uint32_t sb,
                                      uint32_t acc[16][2], int lane) {
#pragma unroll
    for (int kk = 0; kk < 8; kk++) {
        uint32_t a[4] = {U[2 * kk][0], U[2 * kk][1], U[2 * kk + 1][0], U[2 * kk + 1][1]};
#pragma unroll
        for (int nh = 0; nh < 2; nh++) {
            uint32_t b[4][4];
            ldB<BTR>(sb, kk, nh, lane, b);
#pragma unroll
            for (int j = 0; j < 8; j++)
                mma_hh(acc[nh * 8 + j], a,
                       b[j >> 1][(j & 1) * 2], b[j >> 1][(j & 1) * 2 + 1]);
        }
    }
}

// A = f16 C-frags, B from smem non-trans, f32 accum.
__device__ __forceinline__ void mm_fp(const uint32_t Z[16][2], uint32_t sb,
                                      float acc[16][4], int lane) {
#pragma unroll
    for (int kk = 0; kk < 8; kk++) {
        uint32_t a[4] = {Z[2 * kk][0], Z[2 * kk][1], Z[2 * kk + 1][0], Z[2 * kk + 1][1]};
#pragma unroll
        for (int nh = 0; nh < 2; nh++) {
            uint32_t b[4][4];
            ldB<0>(sb, kk, nh, lane, b);
#pragma unroll
            for (int j = 0; j < 8; j++)
                mma_hf(acc[nh * 8 + j], a,
                       b[j >> 1][(j & 1) * 2], b[j >> 1][(j & 1) * 2 + 1]);
        }
    }
}

__device__ __forceinline__ void zacc(float acc[16][4]) {
#pragma unroll
    for (int n = 0; n < 16; n++)
#pragma unroll
        for (int j = 0; j < 4; j++) acc[n][j] = 0.0f;
}
__device__ __forceinline__ void zacc16(uint32_t acc[16][2]) {
#pragma unroll
    for (int n = 0; n < 16; n++) { acc[n][0] = 0u; acc[n][1] = 0u; }
}

// f32 accum (scaled) -> f16 row-major gmem tile (m16 layout)
__device__ __forceinline__ void store_f16(const float acc[16][4],
                                          __half* __restrict__ dst,
                                          int lane, int mo, float scale) {
    int gq = lane >> 2, t = lane & 3;
#pragma unroll
    for (int nt = 0; nt < 16; nt++) {
        int col = nt * 8 + 2 * t;
        *(uint32_t*)(dst + (mo + gq) * 128 + col) =
            pack_h(acc[nt][0] * scale, acc[nt][1] * scale);
        *(uint32_t*)(dst + (mo + 8 + gq) * 128 + col) =
            pack_h(acc[nt][2] * scale, acc[nt][3] * scale);
    }
}

// ===========================================================================
// Kernel 0: ONE prep launch (grid=2).  Also bumps the dataflow epoch.
//   CTA0: G' = (Wq^T Wk / sqrt(H)) * 1024     CTA1: W2 = Wo @ Wv
// ===========================================================================
#define KP_SMEM (2 * 32768)

extern "C" __global__ void __launch_bounds__(256, 1)
k_prep(const float* __restrict__ Wq, const float* __restrict__ Wk,
       const float* __restrict__ Wv, const float* __restrict__ Wo) {
    extern __shared__ char smem[];
    char* a = smem;
    char* b = smem + 32768;
    int tid = threadIdx.x, wid = tid >> 5, lane = tid & 31;
    int mo = wid * 16;
    uint32_t sa = smem_u32(a), sb = smem_u32(b);
    float acc[16][4];

    if (blockIdx.x == 0) {
        if (tid == 0) atomicAdd(&g_epoch, 1);   // new epoch for this replay
        load_w(a, Wq, tid);
        load_w(b, Wk, tid);
        __syncthreads();
        zacc(acc);
        mm_s32<1, 1>(sa, sb, acc, lane, mo);    // G[t1][t2] = sum_h Wq[h][t1] Wk[h][t2]
        store_f16(acc, g_G, lane, mo, RSQRT_H * PRESCALE);
    } else {
        load_w(a, Wo, tid);
        load_w(b, Wv, tid);
        __syncthreads();
        zacc(acc);
        mm_s32<0, 1>(sa, sb, acc, lane, mo);    // W2[o][t] = sum_v Wo[o][v] Wv[v][t]
        store_f16(acc, g_W2, lane, mo, 1.0f);
    }
}

// ===========================================================================
// Fused persistent kernel, NO grid barriers (per-chunk dataflow flags).
// smem: b0=Tn (resident) -> proj stage / b1=G -> P -> W2 / b2=Tpre.
// ===========================================================================
#define KF_SMEM (3 * 32768)

extern "C" __global__ void __launch_bounds__(256, 2)
k_fused(const float* __restrict__ tokens,
        const float* __restrict__ g1, const float* __restrict__ b1v,
        const float* __restrict__ g2, const float* __restrict__ b2v,
        float* __restrict__ out) {
    extern __shared__ char smem[];
    char* b0 = smem;
    char* b1 = smem + 32768;
    char* b2 = smem + 65536;
    int tid = threadIdx.x, wid = tid >> 5, lane = tid & 31;
    int mo = wid * 16;
    int gq = lane >> 2, t = lane & 3;
    int cid = blockIdx.x, base = cid * CH;
    int bb = cid >> 6, lc = cid & 63;          // batch, chunk-in-batch
    uint32_t sb0 = smem_u32(b0), sb1 = smem_u32(b1), sb2 = smem_u32(b2);

    int ep = *((volatile int*)&g_epoch);

    // ============================ PHASE A ==================================
    cp_tile(sb1, g_G, tid);                 // G -> b1 (for U below)
    CP_COMMIT();

    for (int r = wid; r < CH; r += 8) {
        float4 v = ((const float4*)(tokens + (size_t)(base + r) * 128))[lane];
        float s  = v.x + v.y + v.z + v.w;
        float s2 = v.x * v.x + v.y * v.y + v.z * v.z + v.w * v.w;
#pragma unroll
        for (int o = 16; o; o >>= 1) {
            s  += __shfl_xor_sync(0xffffffffu, s, o);
            s2 += __shfl_xor_sync(0xffffffffu, s2, o);
        }
        float mu  = s * (1.0f / 128.0f);
        float var = fmaxf(s2 * (1.0f / 128.0f) - mu * mu, 0.0f);
        float inv = rsqrtf(var + 1e-5f);
        float4 gg = ((const float4*)g1)[lane];
        float4 bb4 = ((const float4*)b1v)[lane];
        float o0 = (v.x - mu) * inv * gg.x + bb4.x;
        float o1 = (v.y - mu) * inv * gg.y + bb4.y;
        float o2 = (v.z - mu) * inv * gg.z + bb4.z;
        float o3 = (v.w - mu) * inv * gg.w + bb4.w;
        uint32_t off = swz(r, lane >> 1) + (lane & 1) * 8;
        *(uint32_t*)(b0 + off)     = pack_h(o0, o1);
        *(uint32_t*)(b0 + off + 4) = pack_h(o2, o3);
    }
    CP_WAIT();
    __syncthreads();

    // T = Tn^T @ Tn -> g_S, then publish tflag
    {
        float acc[16][4];
        zacc(acc);
        mm_s32<1, 1>(sb0, sb0, acc, lane, mo);
        store_f16(acc, g_S + (size_t)cid * TILE, lane, mo, 1.0f);
    }
    __threadfence();                        // all T stores visible GPU-wide
    __syncthreads();
    if (tid == 0) *((volatile int*)&g_tflag[cid]) = ep;

    // U' = Tn @ G'  (f16 acc; B = G trans); lives in registers
    uint32_t Ua[16][2];
    zacc16(Ua);
    mm_s16<1>(sb0, sb1, Ua, lane, mo);

    // ============================ SCAN (warps 0-3) =========================
    // half2 walkers over this CTA's batch; gate each chunk on its tflag;
    // publish progress every 8 chunks (fence + named barrier + one store).
    if (tid < 128) {
        int e = (cid * 128 + tid) & 8191;   // pair index in the batch tile
        const __half2* S = (const __half2*)(g_S + (size_t)bb * NCB * TILE) + e;
        __half2* M = (__half2*)(g_M + (size_t)bb * NCB * TILE) + e;
        float sx = 0.0f, sy = 0.0f;
        for (int g8 = 0; g8 < 8; g8++) {
#pragma unroll
            for (int q = 0; q < 8; q++) {
                while (*((volatile int*)&g_tflag[bb * 64 + g8 * 8 + q]) != ep)
                    __nanosleep(32);
            }
#pragma unroll
            for (int q = 0; q < 8; q++) {
                int c = g8 * 8 + q;
                M[(size_t)c * (TILE / 2)] = __floats2half2_rn(sx, sy);
                __half2 hv = __ldcg(&S[(size_t)c * (TILE / 2)]);
                float2 v = __half22float2(hv);
                sx += v.x;
                sy += v.y;
            }
            __threadfence();
            asm volatile("bar.sync 1, 128;" ::: "memory");
            if (tid == 0)
                *((volatile int*)&g_prog[cid]) = ep * NCB + (g8 + 1) * 8;
        }
    }

    // ================== PHASE C (Tpre-independent part) ====================
    // scores' = U' @ Tn^T  (f16 acc)
    uint32_t accS[16][2];
    zacc16(accS);
    mm_fh<0>(Ua, sb0, accS, lane);

    // masked P -> b1 (own rows only; warp-local)
    {
        __half z = __float2half(0.0f);
#pragma unroll
        for (int nt = 0; nt < 16; nt++) {
            int col = nt * 8 + 2 * t;
            int r0 = mo + gq, r1 = r0 + 8;
            __half2 h0 = *reinterpret_cast<__half2*>(&accS[nt][0]);
            __half2 h1 = *reinterpret_cast<__half2*>(&accS[nt][1]);
            if (col     > r0) h0.x = z;
            if (col + 1 > r0) h0.y = z;
            if (col     > r1) h1.x = z;
            if (col + 1 > r1) h1.y = z;
            *(uint32_t*)(b1 + swz(r0, nt) + (col & 7) * 2) = *reinterpret_cast<uint32_t*>(&h0);
            *(uint32_t*)(b1 + swz(r1, nt) + (col & 7) * 2) = *reinterpret_cast<uint32_t*>(&h1);
        }
    }
    __syncwarp();                           // P rows (own) visible to own warp

    // Z' = P' @ Tn  (A = P own rows, B = Tn trans)
    uint32_t accZ[16][2];
    zacc16(accZ);
    mm_s16<1>(sb1, sb0, accZ, lane, mo);

    // ===================== wait for OWN Tpre, finish =======================
    {
        int tgt = ep * NCB + lc + 1;
        volatile int* pp = (volatile int*)&g_prog[bb * 64 + (tid & 63)];
        while (*pp < tgt) __nanosleep(64);
    }
    __syncthreads();                        // all entries confirmed; P dead

    cp_tile(sb2, g_M + (size_t)cid * TILE, tid);   // Tpre -> b2  (group 1)
    CP_COMMIT();
    cp_tile(sb1, g_W2, tid);                       // W2   -> b1  (group 0)
    CP_COMMIT();
    CP_WAIT_G(1);                           // Tpre landed
    __syncthreads();

    // Z' += U' @ Tpre  (Tpre symmetric -> non-trans read)
    mm_fh<0>(Ua, sb2, accZ, lane);

    CP_WAIT_G(0);                           // W2 landed
    __syncthreads();

    // proj' = Z' @ W2^T  (f32 accum)
    float accP[16][4];
    zacc(accP);
    mm_fp(accZ, sb1, accP, lane);

    // proj' -> b0 f16 row-major (raw; final scale applied at LN2 read)
#pragma unroll
    for (int nt = 0; nt < 16; nt++) {
        int col = nt * 8 + 2 * t;
        int r0 = mo + gq, r1 = r0 + 8;
        *(uint32_t*)(b0 + (r0 * 128 + col) * 2) = pack_h(accP[nt][0], accP[nt][1]);
        *(uint32_t*)(b0 + (r1 * 128 + col) * 2) = pack_h(accP[nt][2], accP[nt][3]);
    }
    __syncthreads();                        // proj visible

    // LN2(tokens + FINAL_SCALE * proj') -> out
    for (int r = wid; r < CH; r += 8) {
        float4 tv = ((const float4*)(tokens + (size_t)(base + r) * 128))[lane];
        uint2 pr = *(const uint2*)(b0 + (r * 128 + lane * 4) * 2);
        __half2 p0 = *reinterpret_cast<__half2*>(&pr.x);
        __half2 p1 = *reinterpret_cast<__half2*>(&pr.y);
        float x0 = tv.x + FINAL_SCALE * __half2float(p0.x);
        float x1 = tv.y + FINAL_SCALE * __half2float(p0.y);
        float x2 = tv.z + FINAL_SCALE * __half2float(p1.x);
        float x3 = tv.w + FINAL_SCALE * __half2float(p1.y);
        float s  = x0 + x1 + x2 + x3;
        float s2 = x0 * x0 + x1 * x1 + x2 * x2 + x3 * x3;
#pragma unroll
        for (int o = 16; o; o >>= 1) {
            s  += __shfl_xor_sync(0xffffffffu, s, o);
            s2 += __shfl_xor_sync(0xffffffffu, s2, o);
        }
        float mu  = s * (1.0f / 128.0f);
        float var = fmaxf(s2 * (1.0f / 128.0f) - mu * mu, 0.0f);
        float inv = rsqrtf(var + 1e-5f);
        float4 gg = ((const float4*)g2)[lane];
        float4 bb4 = ((const float4*)b2v)[lane];
        float4 o4;
        o4.x = (x0 - mu) * inv * gg.x + bb4.x;
        o4.y = (x1 - mu) * inv * gg.y + bb4.y;
        o4.z = (x2 - mu) * inv * gg.z + bb4.z;
        o4.w = (x3 - mu) * inv * gg.w + bb4.w;
        ((float4*)(out + (size_t)(base + r) * 128))[lane] = o4;
    }
}

// ===========================================================================
extern "C" void kernel_launch(void* const* d_in, const int* in_sizes, int n_in,
                              void* d_out, int out_size) {
    const float* tokens = (const float*)d_in[0];
    const float* Wq = (const float*)d_in[1];
    const float* Wk = (const float*)d_in[2];
    const float* Wv = (const float*)d_in[3];
    const float* Wo = (const float*)d_in[4];
    const float* g1 = (const float*)d_in[5];
    const float* b1 = (const float*)d_in[6];
    const float* g2 = (const float*)d_in[7];
    const float* b2 = (const float*)d_in[8];
    float* out = (float*)d_out;

    cudaFuncSetAttribute(k_prep,  cudaFuncAttributeMaxDynamicSharedMemorySize, KP_SMEM);
    cudaFuncSetAttribute(k_fused, cudaFuncAttributeMaxDynamicSharedMemorySize, KF_SMEM);

    k_prep<<<2, 256, KP_SMEM>>>(Wq, Wk, Wv, Wo);
    k_fused<<<NCHUNK, 256, KF_SMEM>>>(tokens, g1, b1, g2, b2, out);
}

// round 15
// speedup vs baseline: 1.3373x; 1.3373x over previous
#include <cuda_runtime.h>
#include <cuda_fp16.h>
#include <stdint.h>

// ---------------------------------------------------------------------------
// Linear attention (causal QK^T, NO softmax) via chunked prefix-state, with
// projections folded into G' = (Wq^T Wk / sqrt(H)) * 1024 and W2 = Wo Wv:
//   U' = Tn G' ; scores' = U' Tn^T ; Z' = tril(scores') Tn + U' Tpre
//   out = LN2(x + (0.1/1024) * Z' W2^T)
// T_c = Tn_c^T Tn_c, Tpre = exclusive prefix sum of T over chunks (per batch).
// R13 structure, but the two GRID-wide barriers are replaced by PER-BATCH
// barriers (64 CTAs each): arrival = one epoch-valued flag store per CTA (no
// atomics, no resets -> graph-replay safe); wait = threads 0..63 poll their
// own batch's 64 flags (single-thread-per-flag, coarse).  The 4 batches
// pipeline independently.  256 threads, m16 x n128 warp tiles, f16
// accumulators, 2 CTAs/SM, all 256 CTAs co-resident (spin-safe).
// ---------------------------------------------------------------------------

#define NB      4
#define NSEQ    8192
#define CH      128
#define NCB     (NSEQ / CH)        // 64
#define NCHUNK  (NB * NCB)         // 256
#define TILE    16384              // 128*128
#define RSQRT_H 0.08838834764831845f
#define PRESCALE 1024.0f
#define FINAL_SCALE (0.1f / 1024.0f)

__device__ __half g_S [NCHUNK * TILE];   // per-chunk gram T_c
__device__ __half g_M [NCHUNK * TILE];   // exclusive prefix Tpre
__device__ __half g_G [TILE];            // (Wq^T Wk / sqrt(H)) * 1024
__device__ __half g_W2[TILE];            // Wo @ Wv

// per-batch barrier flags (zero-init; epoch grows monotonically per replay)
__device__ int g_ep = 0;
__device__ int g_f1[NCHUNK];
__device__ int g_f2[NCHUNK];

// Per-batch barrier: CTA (bb, lc) arrives with value ep on flags[bb*64+lc];
// threads 0..63 wait until ALL 64 CTAs of batch bb have arrived.
__device__ __forceinline__ void batch_bar(int* flags, int bb, int lc, int ep) {
    __syncthreads();
    __threadfence();                         // publish this CTA's data
    if (threadIdx.x == 0)
        *((volatile int*)&flags[bb * 64 + lc]) = ep;
    if (threadIdx.x < 64) {
        volatile int* f = (volatile int*)&flags[bb * 64 + threadIdx.x];
        while (*f < ep) __nanosleep(64);
    }
    __syncthreads();
    __threadfence();                         // acquire side
}

// =========================== helpers =======================================
__device__ __forceinline__ uint32_t smem_u32(const void* p) {
    uint32_t a;
    asm("{ .reg .u64 t; cvta.to.shared.u64 t, %1; cvt.u32.u64 %0, t; }"
        : "=r"(a) : "l"(p));
    return a;
}

__device__ __forceinline__ uint32_t swz(int row, int colg) {
    return (uint32_t)(row * 256) + (uint32_t)(((colg ^ (row & 7)) << 4));
}

__device__ __forceinline__ uint32_t pack_h(float lo, float hi) {
    __half2 h = __floats2half2_rn(lo, hi);
    return *reinterpret_cast<uint32_t*>(&h);
}

__device__ __forceinline__ void ldm4(uint32_t addr, uint32_t r[4]) {
    asm volatile("ldmatrix.sync.aligned.m8n8.x4.shared.b16 {%0,%1,%2,%3}, [%4];"
                 : "=r"(r[0]), "=r"(r[1]), "=r"(r[2]), "=r"(r[3]) : "r"(addr));
}
__device__ __forceinline__ void ldm4t(uint32_t addr, uint32_t r[4]) {
    asm volatile("ldmatrix.sync.aligned.m8n8.x4.trans.shared.b16 {%0,%1,%2,%3}, [%4];"
                 : "=r"(r[0]), "=r"(r[1]), "=r"(r[2]), "=r"(r[3]) : "r"(addr));
}

__device__ __forceinline__ void mma_hf(float* c, const uint32_t a[4],
                                       uint32_t b0, uint32_t b1) {
    asm volatile(
        "mma.sync.aligned.m16n8k16.row.col.f32.f16.f16.f32 "
        "{%0,%1,%2,%3},{%4,%5,%6,%7},{%8,%9},{%0,%1,%2,%3};"
        : "+f"(c[0]), "+f"(c[1]), "+f"(c[2]), "+f"(c[3])
        : "r"(a[0]), "r"(a[1]), "r"(a[2]), "r"(a[3]), "r"(b0), "r"(b1));
}
__device__ __forceinline__ void mma_hh(uint32_t c[2], const uint32_t a[4],
                                       uint32_t b0, uint32_t b1) {
    asm volatile(
        "mma.sync.aligned.m16n8k16.row.col.f16.f16.f16.f16 "
        "{%0,%1},{%2,%3,%4,%5},{%6,%7},{%0,%1};"
        : "+r"(c[0]), "+r"(c[1])
        : "r"(a[0]), "r"(a[1]), "r"(a[2]), "r"(a[3]), "r"(b0), "r"(b1));
}

// cp.async 128x128 f16 gmem tile -> swizzled smem tile (256 threads)
__device__ __forceinline__ void cp_tile(uint32_t dst, const __half* __restrict__ src,
                                        int tid) {
#pragma unroll
    for (int i = 0; i < 8; i++) {
        int idx = tid + i * 256;
        int row = idx >> 4, g = idx & 15;
        asm volatile("cp.async.cg.shared.global [%0], [%1], 16;"
                     :: "r"(dst + swz(row, g)),
                        "l"((const void*)(((const uint4*)src) + idx)));
    }
}
#define CP_COMMIT() asm volatile("cp.async.commit_group;" ::: "memory")
#define CP_WAIT()   asm volatile("cp.async.wait_all;" ::: "memory")
#define CP_WAIT_G(n) asm volatile("cp.async.wait_group %0;" :: "n"(n) : "memory")

// fp32 row-major 128x128 gmem -> f16 swizzled smem tile (256 threads)
__device__ __forceinline__ void load_w(char* dst, const float* __restrict__ W, int tid) {
#pragma unroll
    for (int i = 0; i < 8; i++) {
        int idx = tid + i * 256;
        int row = idx >> 4, g = idx & 15;
        const float4* p = (const float4*)(W + row * 128 + g * 8);
        float4 v0 = p[0], v1 = p[1];
        uint4 o;
        o.x = pack_h(v0.x, v0.y);  o.y = pack_h(v0.z, v0.w);
        o.z = pack_h(v1.x, v1.y);  o.w = pack_h(v1.z, v1.w);
        *(uint4*)(dst + swz(row, g)) = o;
    }
}

// B-operand ldmatrix for n-half nh (8 n8-tiles), k-block kk.
template <int BTR>
__device__ __forceinline__ void ldB(uint32_t sb, int kk, int nh, int lane,
                                    uint32_t b[4][4]) {
#pragma unroll
    for (int q = 0; q < 4; q++) {
        int idx = nh * 4 + q;
        if (!BTR) {
            ldm4(sb + swz(idx * 16 + ((lane >> 4) << 3) + (lane & 7),
                          kk * 2 + ((lane >> 3) & 1)), b[q]);
        } else {
            ldm4t(sb + swz(kk * 16 + ((lane >> 3) & 1) * 8 + (lane & 7),
                           idx * 2 + (lane >> 4)), b[q]);
        }
    }
}

// m16 x n128 x k128, A from smem, f32 accum.
template <int ATR, int BTR>
__device__ __forceinline__ void mm_s32(uint32_t sa, uint32_t sb,
                                       float acc[16][4], int lane, int mo) {
#pragma unroll
    for (int kk = 0; kk < 8; kk++) {
        uint32_t a[4];
        if (!ATR) {
            ldm4(sa + swz(mo + (lane & 15), kk * 2 + (lane >> 4)), a);
        } else {
            ldm4t(sa + swz(kk * 16 + ((lane >> 4) << 3) + (lane & 7),
                           (mo >> 3) + ((lane >> 3) & 1)), a);
        }
#pragma unroll
        for (int nh = 0; nh < 2; nh++) {
            uint32_t b[4][4];
            ldB<BTR>(sb, kk, nh, lane, b);
#pragma unroll
            for (int j = 0; j < 8; j++)
                mma_hf(acc[nh * 8 + j], a,
                       b[j >> 1][(j & 1) * 2], b[j >> 1][(j & 1) * 2 + 1]);
        }
    }
}

// m16 x n128 x k128, A from smem (non-trans), f16 accum.
template <int BTR>
__device__ __forceinline__ void mm_s16(uint32_t sa, uint32_t sb,
                                       uint32_t acc[16][2], int lane, int mo) {
#pragma unroll
    for (int kk = 0; kk < 8; kk++) {
        uint32_t a[4];
        ldm4(sa + swz(mo + (lane & 15), kk * 2 + (lane >> 4)), a);
#pragma unroll
        for (int nh = 0; nh < 2; nh++) {
            uint32_t b[4][4];
            ldB<BTR>(sb, kk, nh, lane, b);
#pragma unroll
            for (int j = 0; j < 8; j++)
                mma_hh(acc[nh * 8 + j], a,
                       b[j >> 1][(j & 1) * 2], b[j >> 1][(j & 1) * 2 + 1]);
        }
    }
}

// Fused dual MMA: A = f16 C-frags (identity), two B tiles (both non-trans),
// two f16 accumulators.  32 independent accumulate chains.
__device__ __forceinline__ void mm_dual(const uint32_t U[16][2],
                                        uint32_t sbA, uint32_t sbB,
                                        uint32_t accA[16][2], uint32_t accB[16][2],
                                        int lane) {
#pragma unroll
    for (int kk = 0; kk < 8; kk++) {
        uint32_t a[4] = {U[2 * kk][0], U[2 * kk][1], U[2 * kk + 1][0], U[2 * kk + 1][1]};
        {
            uint32_t b[4][4];
#pragma unroll
            for (int nh = 0; nh < 2; nh++) {
                ldB<0>(sbA, kk, nh, lane, b);
#pragma unroll
                for (int j = 0; j < 8; j++)
                    mma_hh(accA[nh * 8 + j], a,
                           b[j >> 1][(j & 1) * 2], b[j >> 1][(j & 1) * 2 + 1]);
            }
        }
        {
            uint32_t b[4][4];
#pragma unroll
            for (int nh = 0; nh < 2; nh++) {
                ldB<0>(sbB, kk, nh, lane, b);
#pragma unroll
                for (int j = 0; j < 8; j++)
                    mma_hh(accB[nh * 8 + j], a,
                           b[j >> 1][(j & 1) * 2], b[j >> 1][(j & 1) * 2 + 1]);
            }
        }
    }
}

// proj: A = f16 C-frags, B non-trans, f32 accum.
__device__ __forceinline__ void mm_fp(const uint32_t Z[16][2], uint32_t sb,
                                      float acc[16][4], int lane) {
#pragma unroll
    for (int kk = 0; kk < 8; kk++) {
        uint32_t a[4] = {Z[2 * kk][0], Z[2 * kk][1], Z[2 * kk + 1][0], Z[2 * kk + 1][1]};
#pragma unroll
        for (int nh = 0; nh < 2; nh++) {
            uint32_t b[4][4];
            ldB<0>(sb, kk, nh, lane, b);
#pragma unroll
            for (int j = 0; j < 8; j++)
                mma_hf(acc[nh * 8 + j], a,
                       b[j >> 1][(j & 1) * 2], b[j >> 1][(j & 1) * 2 + 1]);
        }
    }
}

__device__ __forceinline__ void zacc(float acc[16][4]) {
#pragma unroll
    for (int n = 0; n < 16; n++)
#pragma unroll
        for (int j = 0; j < 4; j++) acc[n][j] = 0.0f;
}
__device__ __forceinline__ void zacc16(uint32_t acc[16][2]) {
#pragma unroll
    for (int n = 0; n < 16; n++) { acc[n][0] = 0u; acc[n][1] = 0u; }
}

// f32 accum (scaled) -> f16 row-major gmem tile (m16 layout)
__device__ __forceinline__ void store_f16(const float acc[16][4],
                                          __half* __restrict__ dst,
                                          int lane, int mo, float scale) {
    int gq = lane >> 2, t = lane & 3;
#pragma unroll
    for (int nt = 0; nt < 16; nt++) {
        int col = nt * 8 + 2 * t;
        *(uint32_t*)(dst + (mo + gq) * 128 + col) =
            pack_h(acc[nt][0] * scale, acc[nt][1] * scale);
        *(uint32_t*)(dst + (mo + 8 + gq) * 128 + col) =
            pack_h(acc[nt][2] * scale, acc[nt][3] * scale);
    }
}

// ===========================================================================
// Kernel 0: ONE prep launch (grid=2).  Also bumps the epoch.
//   CTA0: G' = (Wq^T Wk / sqrt(H)) * 1024     CTA1: W2 = Wo @ Wv
// ===========================================================================
#define KP_SMEM (2 * 32768)

extern "C" __global__ void __launch_bounds__(256, 1)
k_prep(const float* __restrict__ Wq, const float* __restrict__ Wk,
       const float* __restrict__ Wv, const float* __restrict__ Wo) {
    extern __shared__ char smem[];
    char* a = smem;
    char* b = smem + 32768;
    int tid = threadIdx.x, wid = tid >> 5, lane = tid & 31;
    int mo = wid * 16;
    uint32_t sa = smem_u32(a), sb = smem_u32(b);
    float acc[16][4];

    if (blockIdx.x == 0) {
        if (tid == 0) atomicAdd(&g_ep, 1);      // new epoch for this replay
        load_w(a, Wq, tid);
        load_w(b, Wk, tid);
        __syncthreads();
        zacc(acc);
        mm_s32<1, 1>(sa, sb, acc, lane, mo);    // G[t1][t2] = sum_h Wq[h][t1] Wk[h][t2]
        store_f16(acc, g_G, lane, mo, RSQRT_H * PRESCALE);
    } else {
        load_w(a, Wo, tid);
        load_w(b, Wv, tid);
        __syncthreads();
        zacc(acc);
        mm_s32<0, 1>(sa, sb, acc, lane, mo);    // W2[o][t] = sum_v Wo[o][v] Wv[v][t]
        store_f16(acc, g_W2, lane, mo, 1.0f);
    }
}

// ===========================================================================
// Fused persistent kernel.  smem: b0=Tn (resident) -> proj / b1=G->P / b2=Tpre->W2.
// U' computed in phase A, carried in registers across both per-batch barriers.
// ===========================================================================
#define KF_SMEM (3 * 32768)

extern "C" __global__ void __launch_bounds__(256, 2)
k_fused(const float* __restrict__ tokens,
        const float* __restrict__ g1, const float* __restrict__ b1v,
        const float* __restrict__ g2, const float* __restrict__ b2v,
        float* __restrict__ out) {
    extern __shared__ char smem[];
    char* b0 = smem;
    char* b1 = smem + 32768;
    char* b2 = smem + 65536;
    int tid = threadIdx.x, wid = tid >> 5, lane = tid & 31;
    int mo = wid * 16;
    int gq = lane >> 2, t = lane & 3;
    int cid = blockIdx.x, base = cid * CH;
    int bb = cid >> 6, lc = cid & 63;           // batch, chunk-in-batch
    uint32_t sb0 = smem_u32(b0), sb1 = smem_u32(b1), sb2 = smem_u32(b2);

    int ep = *((volatile int*)&g_ep);

    // ============================ PHASE A ==================================
    cp_tile(sb1, g_G, tid);                 // G -> b1 (for U below)
    CP_COMMIT();

    for (int r = wid; r < CH; r += 8) {
        float4 v = ((const float4*)(tokens + (size_t)(base + r) * 128))[lane];
        float s  = v.x + v.y + v.z + v.w;
        float s2 = v.x * v.x + v.y * v.y + v.z * v.z + v.w * v.w;
#pragma unroll
        for (int o = 16; o; o >>= 1) {
            s  += __shfl_xor_sync(0xffffffffu, s, o);
            s2 += __shfl_xor_sync(0xffffffffu, s2, o);
        }
        float mu  = s * (1.0f / 128.0f);
        float var = fmaxf(s2 * (1.0f / 128.0f) - mu * mu, 0.0f);
        float inv = rsqrtf(var + 1e-5f);
        float4 gg = ((const float4*)g1)[lane];
        float4 bb4 = ((const float4*)b1v)[lane];
        float o0 = (v.x - mu) * inv * gg.x + bb4.x;
        float o1 = (v.y - mu) * inv * gg.y + bb4.y;
        float o2 = (v.z - mu) * inv * gg.z + bb4.z;
        float o3 = (v.w - mu) * inv * gg.w + bb4.w;
        uint32_t off = swz(r, lane >> 1) + (lane & 1) * 8;
        *(uint32_t*)(b0 + off)     = pack_h(o0, o1);
        *(uint32_t*)(b0 + off + 4) = pack_h(o2, o3);
    }
    CP_WAIT();
    __syncthreads();

    // T = Tn^T @ Tn -> g_S  (f32 accum)
    {
        float acc[16][4];
        zacc(acc);
        mm_s32<1, 1>(sb0, sb0, acc, lane, mo);
        store_f16(acc, g_S + (size_t)cid * TILE, lane, mo, 1.0f);
    }

    // U' = Tn @ G'  (f16 acc; B = G trans); lives in registers across barriers
    uint32_t Ua[16][2];
    zacc16(Ua);
    mm_s16<1>(sb0, sb1, Ua, lane, mo);

    batch_bar(g_f1, bb, lc, ep);            // own batch's T all visible

    // ============================ PHASE B ==================================
    // half2 scan over OWN batch: 128 walkers/CTA, each owns one element pair.
    if (tid < 128) {
        int e = (cid * 128 + tid) & 8191;   // pair index in the batch tile
        const __half2* S = (const __half2*)(g_S + (size_t)bb * NCB * TILE) + e;
        __half2* M = (__half2*)(g_M + (size_t)bb * NCB * TILE) + e;
        float sx = 0.0f, sy = 0.0f;
#pragma unroll 8
        for (int c = 0; c < NCB; c++) {
            M[(size_t)c * (TILE / 2)] = __floats2half2_rn(sx, sy);
            float2 v = __half22float2(S[(size_t)c * (TILE / 2)]);
            sx += v.x;
            sy += v.y;
        }
    }

    batch_bar(g_f2, bb, lc, ep);            // own batch's Tpre all visible

    // ============================ PHASE C ==================================
    cp_tile(sb2, g_M + (size_t)cid * TILE, tid);   // Tpre -> b2
    CP_COMMIT();
    CP_WAIT();
    __syncthreads();                        // S1: Tpre in smem (G in b1 dead)

    // fused: scores' = U' Tn^T  and  Z' = U' Tpre  (Tpre symmetric -> non-trans)
    uint32_t accS[16][2], accZ[16][2];
    zacc16(accS);
    zacc16(accZ);
    mm_dual(Ua, sb0, sb2, accS, accZ, lane);
    __syncthreads();                        // S2: Tpre reads done everywhere

    cp_tile(sb2, g_W2, tid);                // W2 -> b2 under the P store + Z mma
    CP_COMMIT();

    // masked P -> b1 (own rows only; warp-local)
    {
        __half z = __float2half(0.0f);
#pragma unroll
        for (int nt = 0; nt < 16; nt++) {
            int col = nt * 8 + 2 * t;
            int r0 = mo + gq, r1 = r0 + 8;
            __half2 h0 = *reinterpret_cast<__half2*>(&accS[nt][0]);
            __half2 h1 = *reinterpret_cast<__half2*>(&accS[nt][1]);
            if (col     > r0) h0.x = z;
            if (col + 1 > r0) h0.y = z;
            if (col     > r1) h1.x = z;
            if (col + 1 > r1) h1.y = z;
            *(uint32_t*)(b1 + swz(r0, nt) + (col & 7) * 2) = *reinterpret_cast<uint32_t*>(&h0);
            *(uint32_t*)(b1 + swz(r1, nt) + (col & 7) * 2) = *reinterpret_cast<uint32_t*>(&h1);
        }
    }
    __syncwarp();                           // P rows (own) visible to own warp

    // Z' += P' @ Tn  (A = P own rows, B = Tn trans)
    mm_s16<1>(sb1, sb0, accZ, lane, mo);

    CP_WAIT();
    __syncthreads();                        // S3: W2 ready; Tn, P dead everywhere

    // proj' = Z' @ W2^T  (f32 accum; A = accZ frags directly)
    float accP[16][4];
    zacc(accP);
    mm_fp(accZ, sb2, accP, lane);

    // proj' -> b0 f16 row-major (raw; final scale applied at LN2 read)
#pragma unroll
    for (int nt = 0; nt < 16; nt++) {
        int col = nt * 8 + 2 * t;
        int r0 = mo + gq, r1 = r0 + 8;
        *(uint32_t*)(b0 + (r0 * 128 + col) * 2) = pack_h(accP[nt][0], accP[nt][1]);
        *(uint32_t*)(b0 + (r1 * 128 + col) * 2) = pack_h(accP[nt][2], accP[nt][3]);
    }
    __syncthreads();                        // S4: proj visible

    // LN2(tokens + FINAL_SCALE * proj') -> out
    for (int r = wid; r < CH; r += 8) {
        float4 tv = ((const float4*)(tokens + (size_t)(base + r) * 128))[lane];
        uint2 pr = *(const uint2*)(b0 + (r * 128 + lane * 4) * 2);
        __half2 p0 = *reinterpret_cast<__half2*>(&pr.x);
        __half2 p1 = *reinterpret_cast<__half2*>(&pr.y);
        float x0 = tv.x + FINAL_SCALE * __half2float(p0.x);
        float x1 = tv.y + FINAL_SCALE * __half2float(p0.y);
        float x2 = tv.z + FINAL_SCALE * __half2float(p1.x);
        float x3 = tv.w + FINAL_SCALE * __half2float(p1.y);
        float s  = x0 + x1 + x2 + x3;
        float s2 = x0 * x0 + x1 * x1 + x2 * x2 + x3 * x3;
#pragma unroll
        for (int o = 16; o; o >>= 1) {
            s  += __shfl_xor_sync(0xffffffffu, s, o);
            s2 += __shfl_xor_sync(0xffffffffu, s2, o);
        }
        float mu  = s * (1.0f / 128.0f);
        float var = fmaxf(s2 * (1.0f / 128.0f) - mu * mu, 0.0f);
        float inv = rsqrtf(var + 1e-5f);
        float4 gg = ((const float4*)g2)[lane];
        float4 bb4 = ((const float4*)b2v)[lane];
        float4 o4;
        o4.x = (x0 - mu) * inv * gg.x + bb4.x;
        o4.y = (x1 - mu) * inv * gg.y + bb4.y;
        o4.z = (x2 - mu) * inv * gg.z + bb4.z;
        o4.w = (x3 - mu) * inv * gg.w + bb4.w;
        ((float4*)(out + (size_t)(base + r) * 128))[lane] = o4;
    }
}

// ===========================================================================
extern "C" void kernel_launch(void* const* d_in, const int* in_sizes, int n_in,
                              void* d_out, int out_size) {
    const float* tokens = (const float*)d_in[0];
    const float* Wq = (const float*)d_in[1];
    const float* Wk = (const float*)d_in[2];
    const float* Wv = (const float*)d_in[3];
    const float* Wo = (const float*)d_in[4];
    const float* g1 = (const float*)d_in[5];
    const float* b1 = (const float*)d_in[6];
    const float* g2 = (const float*)d_in[7];
    const float* b2 = (const float*)d_in[8];
    float* out = (float*)d_out;

    cudaFuncSetAttribute(k_prep,  cudaFuncAttributeMaxDynamicSharedMemorySize, KP_SMEM);
    cudaFuncSetAttribute(k_fused, cudaFuncAttributeMaxDynamicSharedMemorySize, KF_SMEM);

    k_prep<<<2, 256, KP_SMEM>>>(Wq, Wk, Wv, Wo);
    k_fused<<<NCHUNK, 256, KF_SMEM>>>(tokens, g1, b1, g2, b2, out);
}

// round 16
// speedup vs baseline: 1.4753x; 1.1032x over previous
#include <cuda_runtime.h>
#include <cuda_fp16.h>
#include <stdint.h>

// ---------------------------------------------------------------------------
// Linear attention (causal QK^T, NO softmax) via chunked prefix-state, with
// projections folded into G' = (Wq^T Wk / sqrt(H)) * 1024 and W2 = Wo Wv:
//   U' = Tn G' ; scores' = U' Tn^T ; Z' = tril(scores') Tn + U' Tpre
//   out = LN2(x + (0.1/1024) * Z' W2^T)
// T_c = Tn_c^T Tn_c, Tpre = exclusive prefix sum of T over chunks (per batch).
// R13 structure with (a) PER-BATCH barriers using the R13 mechanism (atomic
// counter + generation, ONE thread polls ONE address; 4 independent padded
// (cnt,gen) pairs -> 4x less arrival serialization and skew coupling), and
// (b) W2 prefetched in a separate cp.async group right after the barrier so
// its load is off the critical path (P reuses Tpre's buffer instead).
// 256 threads, m16 x n128 warp tiles, f16 accumulators, 2 CTAs/SM, all 256
// CTAs co-resident (spin-safe).
// ---------------------------------------------------------------------------

#define NB      4
#define NSEQ    8192
#define CH      128
#define NCB     (NSEQ / CH)        // 64
#define NCHUNK  (NB * NCB)         // 256
#define TILE    16384              // 128*128
#define RSQRT_H 0.08838834764831845f
#define PRESCALE 1024.0f
#define FINAL_SCALE (0.1f / 1024.0f)

__device__ __half g_S [NCHUNK * TILE];   // per-chunk gram T_c
__device__ __half g_M [NCHUNK * TILE];   // exclusive prefix Tpre
__device__ __half g_G [TILE];            // (Wq^T Wk / sqrt(H)) * 1024
__device__ __half g_W2[TILE];            // Wo @ Wv

// Per-batch barrier state: each batch has (cnt, gen) on its OWN 128B line.
// gen grows monotonically across graph replays (no reset hazard).
struct __align__(128) BarSlot { int cnt; int gen; int pad[30]; };
__device__ BarSlot g_bar1[NB];
__device__ BarSlot g_bar2[NB];

// R13-mechanism barrier at batch scope: arrival = atomicAdd on batch counter;
// wait = ONE thread polling the batch's gen word.
__device__ __forceinline__ void batch_bar(BarSlot* s, int bb) {
    __syncthreads();
    if (threadIdx.x == 0) {
        __threadfence();
        int gen = *((volatile int*)&s[bb].gen);
        if (atomicAdd(&s[bb].cnt, 1) == NCB - 1) {
            s[bb].cnt = 0;
            __threadfence();
            atomicExch(&s[bb].gen, gen + 1);
        } else {
            while (*((volatile int*)&s[bb].gen) == gen) __nanosleep(32);
        }
        __threadfence();
    }
    __syncthreads();
}

// =========================== helpers =======================================
__device__ __forceinline__ uint32_t smem_u32(const void* p) {
    uint32_t a;
    asm("{ .reg .u64 t; cvta.to.shared.u64 t, %1; cvt.u32.u64 %0, t; }"
        : "=r"(a) : "l"(p));
    return a;
}

__device__ __forceinline__ uint32_t swz(int row, int colg) {
    return (uint32_t)(row * 256) + (uint32_t)(((colg ^ (row & 7)) << 4));
}

__device__ __forceinline__ uint32_t pack_h(float lo, float hi) {
    __half2 h = __floats2half2_rn(lo, hi);
    return *reinterpret_cast<uint32_t*>(&h);
}

__device__ __forceinline__ void ldm4(uint32_t addr, uint32_t r[4]) {
    asm volatile("ldmatrix.sync.aligned.m8n8.x4.shared.b16 {%0,%1,%2,%3}, [%4];"
                 : "=r"(r[0]), "=r"(r[1]), "=r"(r[2]), "=r"(r[3]) : "r"(addr));
}
__device__ __forceinline__ void ldm4t(uint32_t addr, uint32_t r[4]) {
    asm volatile("ldmatrix.sync.aligned.m8n8.x4.trans.shared.b16 {%0,%1,%2,%3}, [%4];"
                 : "=r"(r[0]), "=r"(r[1]), "=r"(r[2]), "=r"(r[3]) : "r"(addr));
}

__device__ __forceinline__ void mma_hf(float* c, const uint32_t a[4],
                                       uint32_t b0, uint32_t b1) {
    asm volatile(
        "mma.sync.aligned.m16n8k16.row.col.f32.f16.f16.f32 "
        "{%0,%1,%2,%3},{%4,%5,%6,%7},{%8,%9},{%0,%1,%2,%3};"
        : "+f"(c[0]), "+f"(c[1]), "+f"(c[2]), "+f"(c[3])
        : "r"(a[0]), "r"(a[1]), "r"(a[2]), "r"(a[3]), "r"(b0), "r"(b1));
}
__device__ __forceinline__ void mma_hh(uint32_t c[2], const uint32_t a[4],
                                       uint32_t b0, uint32_t b1) {
    asm volatile(
        "mma.sync.aligned.m16n8k16.row.col.f16.f16.f16.f16 "
        "{%0,%1},{%2,%3,%4,%5},{%6,%7},{%0,%1};"
        : "+r"(c[0]), "+r"(c[1])
        : "r"(a[0]), "r"(a[1]), "r"(a[2]), "r"(a[3]), "r"(b0), "r"(b1));
}

// cp.async 128x128 f16 gmem tile -> swizzled smem tile (256 threads)
__device__ __forceinline__ void cp_tile(uint32_t dst, const __half* __restrict__ src,
                                        int tid) {
#pragma unroll
    for (int i = 0; i < 8; i++) {
        int idx = tid + i * 256;
        int row = idx >> 4, g = idx & 15;
        asm volatile("cp.async.cg.shared.global [%0], [%1], 16;"
                     :: "r"(dst + swz(row, g)),
                        "l"((const void*)(((const uint4*)src) + idx)));
    }
}
#define CP_COMMIT() asm volatile("cp.async.commit_group;" ::: "memory")
#define CP_WAIT()   asm volatile("cp.async.wait_all;" ::: "memory")
#define CP_WAIT_G(n) asm volatile("cp.async.wait_group %0;" :: "n"(n) : "memory")

// fp32 row-major 128x128 gmem -> f16 swizzled smem tile (256 threads)
__device__ __forceinline__ void load_w(char* dst, const float* __restrict__ W, int tid) {
#pragma unroll
    for (int i = 0; i < 8; i++) {
        int idx = tid + i * 256;
        int row = idx >> 4, g = idx & 15;
        const float4* p = (const float4*)(W + row * 128 + g * 8);
        float4 v0 = p[0], v1 = p[1];
        uint4 o;
        o.x = pack_h(v0.x, v0.y);  o.y = pack_h(v0.z, v0.w);
        o.z = pack_h(v1.x, v1.y);  o.w = pack_h(v1.z, v1.w);
        *(uint4*)(dst + swz(row, g)) = o;
    }
}

// B-operand ldmatrix for n-half nh (8 n8-tiles), k-block kk.
template <int BTR>
__device__ __forceinline__ void ldB(uint32_t sb, int kk, int nh, int lane,
                                    uint32_t b[4][4]) {
#pragma unroll
    for (int q = 0; q < 4; q++) {
        int idx = nh * 4 + q;
        if (!BTR) {
            ldm4(sb + swz(idx * 16 + ((lane >> 4) << 3) + (lane & 7),
                          kk * 2 + ((lane >> 3) & 1)), b[q]);
        } else {
            ldm4t(sb + swz(kk * 16 + ((lane >> 3) & 1) * 8 + (lane & 7),
                           idx * 2 + (lane >> 4)), b[q]);
        }
    }
}

// m16 x n128 x k128, A from smem, f32 accum.
template <int ATR, int BTR>
__device__ __forceinline__ void mm_s32(uint32_t sa, uint32_t sb,
                                       float acc[16][4], int lane, int mo) {
#pragma unroll
    for (int kk = 0; kk < 8; kk++) {
        uint32_t a[4];
        if (!ATR) {
            ldm4(sa + swz(mo + (lane & 15), kk * 2 + (lane >> 4)), a);
        } else {
            ldm4t(sa + swz(kk * 16 + ((lane >> 4) << 3) + (lane & 7),
                           (mo >> 3) + ((lane >> 3) & 1)), a);
        }
#pragma unroll
        for (int nh = 0; nh < 2; nh++) {
            uint32_t b[4][4];
            ldB<BTR>(sb, kk, nh, lane, b);
#pragma unroll
            for (int j = 0; j < 8; j++)
                mma_hf(acc[nh * 8 + j], a,
                       b[j >> 1][(j & 1) * 2], b[j >> 1][(j & 1) * 2 + 1]);
        }
    }
}

// m16 x n128 x k128, A from smem (non-trans), f16 accum.
template <int BTR>
__device__ __forceinline__ void mm_s16(uint32_t sa, uint32_t sb,
                                       uint32_t acc[16][2], int lane, int mo) {
#pragma unroll
    for (int kk = 0; kk < 8; kk++) {
        uint32_t a[4];
        ldm4(sa + swz(mo + (lane & 15), kk * 2 + (lane >> 4)), a);
#pragma unroll
        for (int nh = 0; nh < 2; nh++) {
            uint32_t b[4][4];
            ldB<BTR>(sb, kk, nh, lane, b);
#pragma unroll
            for (int j = 0; j < 8; j++)
                mma_hh(acc[nh * 8 + j], a,
                       b[j >> 1][(j & 1) * 2], b[j >> 1][(j & 1) * 2 + 1]);
        }
    }
}

// Fused dual MMA: A = f16 C-frags (identity), two B tiles (both non-trans),
// two f16 accumulators.  32 independent accumulate chains.
__device__ __forceinline__ void mm_dual(const uint32_t U[16][2],
                                        uint32_t sbA, uint32_t sbB,
                                        uint32_t accA[16][2], uint32_t accB[16][2],
                                        int lane) {
#pragma unroll
    for (int kk = 0; kk < 8; kk++) {
        uint32_t a[4] = {U[2 * kk][0], U[2 * kk][1], U[2 * kk + 1][0], U[2 * kk + 1][1]};
        {
            uint32_t b[4][4];
#pragma unroll
            for (int nh = 0; nh < 2; nh++) {
                ldB<0>(sbA, kk, nh, lane, b);
#pragma unroll
                for (int j = 0; j < 8; j++)
                    mma_hh(accA[nh * 8 + j], a,
                           b[j >> 1][(j & 1) * 2], b[j >> 1][(j & 1) * 2 + 1]);
            }
        }
        {
            uint32_t b[4][4];
#pragma unroll
            for (int nh = 0; nh < 2; nh++) {
                ldB<0>(sbB, kk, nh, lane, b);
#pragma unroll
                for (int j = 0; j < 8; j++)
                    mma_hh(accB[nh * 8 + j], a,
                           b[j >> 1][(j & 1) * 2], b[j >> 1][(j & 1) * 2 + 1]);
            }
        }
    }
}

// proj: A = f16 C-frags, B non-trans, f32 accum.
__device__ __forceinline__ void mm_fp(const uint32_t Z[16][2], uint32_t sb,
                                      float acc[16][4], int lane) {
#pragma unroll
    for (int kk = 0; kk < 8; kk++) {
        uint32_t a[4] = {Z[2 * kk][0], Z[2 * kk][1], Z[2 * kk + 1][0], Z[2 * kk + 1][1]};
#pragma unroll
        for (int nh = 0; nh < 2; nh++) {
            uint32_t b[4][4];
            ldB<0>(sb, kk, nh, lane, b);
#pragma unroll
            for (int j = 0; j < 8; j++)
                mma_hf(acc[nh * 8 + j], a,
                       b[j >> 1][(j & 1) * 2], b[j >> 1][(j & 1) * 2 + 1]);
        }
    }
}

__device__ __forceinline__ void zacc(float acc[16][4]) {
#pragma unroll
    for (int n = 0; n < 16; n++)
#pragma unroll
        for (int j = 0; j < 4; j++) acc[n][j] = 0.0f;
}
__device__ __forceinline__ void zacc16(uint32_t acc[16][2]) {
#pragma unroll
    for (int n = 0; n < 16; n++) { acc[n][0] = 0u; acc[n][1] = 0u; }
}

// f32 accum (scaled) -> f16 row-major gmem tile (m16 layout)
__device__ __forceinline__ void store_f16(const float acc[16][4],
                                          __half* __restrict__ dst,
                                          int lane, int mo, float scale) {
    int gq = lane >> 2, t = lane & 3;
#pragma unroll
    for (int nt = 0; nt < 16; nt++) {
        int col = nt * 8 + 2 * t;
        *(uint32_t*)(dst + (mo + gq) * 128 + col) =
            pack_h(acc[nt][0] * scale, acc[nt][1] * scale);
        *(uint32_t*)(dst + (mo + 8 + gq) * 128 + col) =
            pack_h(acc[nt][2] * scale, acc[nt][3] * scale);
    }
}

// ===========================================================================
// Kernel 0: ONE prep launch (grid=2).
//   CTA0: G' = (Wq^T Wk / sqrt(H)) * 1024     CTA1: W2 = Wo @ Wv
// ===========================================================================
#define KP_SMEM (2 * 32768)

extern "C" __global__ void __launch_bounds__(256, 1)
k_prep(const float* __restrict__ Wq, const float* __restrict__ Wk,
       const float* __restrict__ Wv, const float* __restrict__ Wo) {
    extern __shared__ char smem[];
    char* a = smem;
    char* b = smem + 32768;
    int tid = threadIdx.x, wid = tid >> 5, lane = tid & 31;
    int mo = wid * 16;
    uint32_t sa = smem_u32(a), sb = smem_u32(b);
    float acc[16][4];

    if (blockIdx.x == 0) {
        load_w(a, Wq, tid);
        load_w(b, Wk, tid);
        __syncthreads();
        zacc(acc);
        mm_s32<1, 1>(sa, sb, acc, lane, mo);    // G[t1][t2] = sum_h Wq[h][t1] Wk[h][t2]
        store_f16(acc, g_G, lane, mo, RSQRT_H * PRESCALE);
    } else {
        load_w(a, Wo, tid);
        load_w(b, Wv, tid);
        __syncthreads();
        zacc(acc);
        mm_s32<0, 1>(sa, sb, acc, lane, mo);    // W2[o][t] = sum_v Wo[o][v] Wv[v][t]
        store_f16(acc, g_W2, lane, mo, 1.0f);
    }
}

// ===========================================================================
// Fused persistent kernel.  smem: b0=Tn (resident) -> proj stage /
// b1=G -> W2 / b2=Tpre -> P.  U' computed in phase A, carried in registers.
// ===========================================================================
#define KF_SMEM (3 * 32768)

extern "C" __global__ void __launch_bounds__(256, 2)
k_fused(const float* __restrict__ tokens,
        const float* __restrict__ g1, const float* __restrict__ b1v,
        const float* __restrict__ g2, const float* __restrict__ b2v,
        float* __restrict__ out) {
    extern __shared__ char smem[];
    char* b0 = smem;
    char* b1 = smem + 32768;
    char* b2 = smem + 65536;
    int tid = threadIdx.x, wid = tid >> 5, lane = tid & 31;
    int mo = wid * 16;
    int gq = lane >> 2, t = lane & 3;
    int cid = blockIdx.x, base = cid * CH;
    int bb = cid >> 6;                      // batch index
    uint32_t sb0 = smem_u32(b0), sb1 = smem_u32(b1), sb2 = smem_u32(b2);

    // ============================ PHASE A ==================================
    cp_tile(sb1, g_G, tid);                 // G -> b1 (for U below)
    CP_COMMIT();

    for (int r = wid; r < CH; r += 8) {
        float4 v = ((const float4*)(tokens + (size_t)(base + r) * 128))[lane];
        float s  = v.x + v.y + v.z + v.w;
        float s2 = v.x * v.x + v.y * v.y + v.z * v.z + v.w * v.w;
#pragma unroll
        for (int o = 16; o; o >>= 1) {
            s  += __shfl_xor_sync(0xffffffffu, s, o);
            s2 += __shfl_xor_sync(0xffffffffu, s2, o);
        }
        float mu  = s * (1.0f / 128.0f);
        float var = fmaxf(s2 * (1.0f / 128.0f) - mu * mu, 0.0f);
        float inv = rsqrtf(var + 1e-5f);
        float4 gg = ((const float4*)g1)[lane];
        float4 bb4 = ((const float4*)b1v)[lane];
        float o0 = (v.x - mu) * inv * gg.x + bb4.x;
        float o1 = (v.y - mu) * inv * gg.y + bb4.y;
        float o2 = (v.z - mu) * inv * gg.z + bb4.z;
        float o3 = (v.w - mu) * inv * gg.w + bb4.w;
        uint32_t off = swz(r, lane >> 1) + (lane & 1) * 8;
        *(uint32_t*)(b0 + off)     = pack_h(o0, o1);
        *(uint32_t*)(b0 + off + 4) = pack_h(o2, o3);
    }
    CP_WAIT();
    __syncthreads();

    // T = Tn^T @ Tn -> g_S  (f32 accum)
    {
        float acc[16][4];
        zacc(acc);
        mm_s32<1, 1>(sb0, sb0, acc, lane, mo);
        store_f16(acc, g_S + (size_t)cid * TILE, lane, mo, 1.0f);
    }

    // U' = Tn @ G'  (f16 acc; B = G trans); lives in registers across barriers
    uint32_t Ua[16][2];
    zacc16(Ua);
    mm_s16<1>(sb0, sb1, Ua, lane, mo);

    batch_bar(g_bar1, bb);                  // own batch's T all visible

    // ============================ PHASE B ==================================
    // half2 scan over OWN batch: 128 walkers/CTA, each owns one element pair.
    if (tid < 128) {
        int e = (cid * 128 + tid) & 8191;   // pair index in the batch tile
        const __half2* S = (const __half2*)(g_S + (size_t)bb * NCB * TILE) + e;
        __half2* M = (__half2*)(g_M + (size_t)bb * NCB * TILE) + e;
        float sx = 0.0f, sy = 0.0f;
#pragma unroll 8
        for (int c = 0; c < NCB; c++) {
            M[(size_t)c * (TILE / 2)] = __floats2half2_rn(sx, sy);
            float2 v = __half22float2(S[(size_t)c * (TILE / 2)]);
            sx += v.x;
            sy += v.y;
        }
    }

    batch_bar(g_bar2, bb);                  // own batch's Tpre all visible

    // ============================ PHASE C ==================================
    // Tpre -> b2 (group 1) and W2 -> b1 (group 0): W2 load fully overlapped.
    cp_tile(sb2, g_M + (size_t)cid * TILE, tid);
    CP_COMMIT();
    cp_tile(sb1, g_W2, tid);
    CP_COMMIT();
    CP_WAIT_G(1);                           // Tpre landed (W2 may still fly)
    __syncthreads();

    // fused: scores' = U' Tn^T  and  Z' = U' Tpre  (Tpre symmetric -> non-trans)
    uint32_t accS[16][2], accZ[16][2];
    zacc16(accS);
    zacc16(accZ);
    mm_dual(Ua, sb0, sb2, accS, accZ, lane);
    __syncthreads();                        // S2: Tpre reads done everywhere

    // masked P -> b2 (overwrites consumed Tpre; own rows only, warp-local)
    {
        __half z = __float2half(0.0f);
#pragma unroll
        for (int nt = 0; nt < 16; nt++) {
            int col = nt * 8 + 2 * t;
            int r0 = mo + gq, r1 = r0 + 8;
            __half2 h0 = *reinterpret_cast<__half2*>(&accS[nt][0]);
            __half2 h1 = *reinterpret_cast<__half2*>(&accS[nt][1]);
            if (col     > r0) h0.x = z;
            if (col + 1 > r0) h0.y = z;
            if (col     > r1) h1.x = z;
            if (col + 1 > r1) h1.y = z;
            *(uint32_t*)(b2 + swz(r0, nt) + (col & 7) * 2) = *reinterpret_cast<uint32_t*>(&h0);
            *(uint32_t*)(b2 + swz(r1, nt) + (col & 7) * 2) = *reinterpret_cast<uint32_t*>(&h1);
        }
    }
    __syncwarp();                           // P rows (own) visible to own warp

    // Z' += P' @ Tn  (A = P own rows, B = Tn trans)
    mm_s16<1>(sb2, sb0, accZ, lane, mo);

    CP_WAIT_G(0);                           // W2 landed (long ago)
    __syncthreads();                        // S3: W2 usable; Tn, P dead

    // proj' = Z' @ W2^T  (f32 accum; A = accZ frags directly)
    float accP[16][4];
    zacc(accP);
    mm_fp(accZ, sb1, accP, lane);

    // proj' -> b0 f16 row-major (raw; final scale applied at LN2 read)
#pragma unroll
    for (int nt = 0; nt < 16; nt++) {
        int col = nt * 8 + 2 * t;
        int r0 = mo + gq, r1 = r0 + 8;
        *(uint32_t*)(b0 + (r0 * 128 + col) * 2) = pack_h(accP[nt][0], accP[nt][1]);
        *(uint32_t*)(b0 + (r1 * 128 + col) * 2) = pack_h(accP[nt][2], accP[nt][3]);
    }
    __syncthreads();                        // S4: proj visible

    // LN2(tokens + FINAL_SCALE * proj') -> out
    for (int r = wid; r < CH; r += 8) {
        float4 tv = ((const float4*)(tokens + (size_t)(base + r) * 128))[lane];
        uint2 pr = *(const uint2*)(b0 + (r * 128 + lane * 4) * 2);
        __half2 p0 = *reinterpret_cast<__half2*>(&pr.x);
        __half2 p1 = *reinterpret_cast<__half2*>(&pr.y);
        float x0 = tv.x + FINAL_SCALE * __half2float(p0.x);
        float x1 = tv.y + FINAL_SCALE * __half2float(p0.y);
        float x2 = tv.z + FINAL_SCALE * __half2float(p1.x);
        float x3 = tv.w + FINAL_SCALE * __half2float(p1.y);
        float s  = x0 + x1 + x2 + x3;
        float s2 = x0 * x0 + x1 * x1 + x2 * x2 + x3 * x3;
#pragma unroll
        for (int o = 16; o; o >>= 1) {
            s  += __shfl_xor_sync(0xffffffffu, s, o);
            s2 += __shfl_xor_sync(0xffffffffu, s2, o);
        }
        float mu  = s * (1.0f / 128.0f);
        float var = fmaxf(s2 * (1.0f / 128.0f) - mu * mu, 0.0f);
        float inv = rsqrtf(var + 1e-5f);
        float4 gg = ((const float4*)g2)[lane];
        float4 bb4 = ((const float4*)b2v)[lane];
        float4 o4;
        o4.x = (x0 - mu) * inv * gg.x + bb4.x;
        o4.y = (x1 - mu) * inv * gg.y + bb4.y;
        o4.z = (x2 - mu) * inv * gg.z + bb4.z;
        o4.w = (x3 - mu) * inv * gg.w + bb4.w;
        ((float4*)(out + (size_t)(base + r) * 128))[lane] = o4;
    }
}

// ===========================================================================
extern "C" void kernel_launch(void* const* d_in, const int* in_sizes, int n_in,
                              void* d_out, int out_size) {
    const float* tokens = (const float*)d_in[0];
    const float* Wq = (const float*)d_in[1];
    const float* Wk = (const float*)d_in[2];
    const float* Wv = (const float*)d_in[3];
    const float* Wo = (const float*)d_in[4];
    const float* g1 = (const float*)d_in[5];
    const float* b1 = (const float*)d_in[6];
    const float* g2 = (const float*)d_in[7];
    const float* b2 = (const float*)d_in[8];
    float* out = (float*)d_out;

    cudaFuncSetAttribute(k_prep,  cudaFuncAttributeMaxDynamicSharedMemorySize, KP_SMEM);
    cudaFuncSetAttribute(k_fused, cudaFuncAttributeMaxDynamicSharedMemorySize, KF_SMEM);

    k_prep<<<2, 256, KP_SMEM>>>(Wq, Wk, Wv, Wo);
    k_fused<<<NCHUNK, 256, KF_SMEM>>>(tokens, g1, b1, g2, b2, out);
}

// round 17
// speedup vs baseline: 1.4987x; 1.0159x over previous
#include <cuda_runtime.h>
#include <cuda_fp16.h>
#include <stdint.h>

// ---------------------------------------------------------------------------
// Linear attention (causal QK^T, NO softmax) via chunked prefix-state, with
// projections folded into G' = (Wq^T Wk / sqrt(H)) * 1024 and W2 = Wo Wv:
//   U' = Tn G' ; scores' = U' Tn^T ; Z' = tril(scores') Tn + U' Tpre
//   out = LN2(x + (0.1/1024) * Z' W2^T)
// T_c = Tn_c^T Tn_c, Tpre = exclusive prefix sum of T over chunks (per batch).
// R16 base (per-batch barriers, R13 poll mechanism) plus:
//  - P fully register-resident: masked scores C-frags used directly as
//    A-frags for Z = P@Tn (f16 C->A identity).  No P smem round-trip, only
//    2 syncthreads in phase C.
//  - Tpre AND W2 prefetched right after bar2 in separate cp.async groups,
//    overlapped under the scores MMA.
//  - f16 accumulators for T and proj (2x HMMA rate, fewer live regs).
// 256 threads, m16 x n128 warp tiles, 2 CTAs/SM, all 256 CTAs co-resident.
// ---------------------------------------------------------------------------

#define NB      4
#define NSEQ    8192
#define CH      128
#define NCB     (NSEQ / CH)        // 64
#define NCHUNK  (NB * NCB)         // 256
#define TILE    16384              // 128*128
#define RSQRT_H 0.08838834764831845f
#define PRESCALE 1024.0f
#define FINAL_SCALE (0.1f / 1024.0f)

__device__ __half g_S [NCHUNK * TILE];   // per-chunk gram T_c
__device__ __half g_M [NCHUNK * TILE];   // exclusive prefix Tpre
__device__ __half g_G [TILE];            // (Wq^T Wk / sqrt(H)) * 1024
__device__ __half g_W2[TILE];            // Wo @ Wv

// Per-batch barrier state: each batch has (cnt, gen) on its OWN 128B line.
// gen grows monotonically across graph replays (no reset hazard).
struct __align__(128) BarSlot { int cnt; int gen; int pad[30]; };
__device__ BarSlot g_bar1[NB];
__device__ BarSlot g_bar2[NB];

// R13-mechanism barrier at batch scope: arrival = atomicAdd on batch counter;
// wait = ONE thread polling the batch's gen word.
__device__ __forceinline__ void batch_bar(BarSlot* s, int bb) {
    __syncthreads();
    if (threadIdx.x == 0) {
        __threadfence();
        int gen = *((volatile int*)&s[bb].gen);
        if (atomicAdd(&s[bb].cnt, 1) == NCB - 1) {
            s[bb].cnt = 0;
            __threadfence();
            atomicExch(&s[bb].gen, gen + 1);
        } else {
            while (*((volatile int*)&s[bb].gen) == gen) __nanosleep(32);
        }
        __threadfence();
    }
    __syncthreads();
}

// =========================== helpers =======================================
__device__ __forceinline__ uint32_t smem_u32(const void* p) {
    uint32_t a;
    asm("{ .reg .u64 t; cvta.to.shared.u64 t, %1; cvt.u32.u64 %0, t; }"
        : "=r"(a) : "l"(p));
    return a;
}

__device__ __forceinline__ uint32_t swz(int row, int colg) {
    return (uint32_t)(row * 256) + (uint32_t)(((colg ^ (row & 7)) << 4));
}

__device__ __forceinline__ uint32_t pack_h(float lo, float hi) {
    __half2 h = __floats2half2_rn(lo, hi);
    return *reinterpret_cast<uint32_t*>(&h);
}

__device__ __forceinline__ void ldm4(uint32_t addr, uint32_t r[4]) {
    asm volatile("ldmatrix.sync.aligned.m8n8.x4.shared.b16 {%0,%1,%2,%3}, [%4];"
                 : "=r"(r[0]), "=r"(r[1]), "=r"(r[2]), "=r"(r[3]) : "r"(addr));
}
__device__ __forceinline__ void ldm4t(uint32_t addr, uint32_t r[4]) {
    asm volatile("ldmatrix.sync.aligned.m8n8.x4.trans.shared.b16 {%0,%1,%2,%3}, [%4];"
                 : "=r"(r[0]), "=r"(r[1]), "=r"(r[2]), "=r"(r[3]) : "r"(addr));
}

__device__ __forceinline__ void mma_hf(float* c, const uint32_t a[4],
                                       uint32_t b0, uint32_t b1) {
    asm volatile(
        "mma.sync.aligned.m16n8k16.row.col.f32.f16.f16.f32 "
        "{%0,%1,%2,%3},{%4,%5,%6,%7},{%8,%9},{%0,%1,%2,%3};"
        : "+f"(c[0]), "+f"(c[1]), "+f"(c[2]), "+f"(c[3])
        : "r"(a[0]), "r"(a[1]), "r"(a[2]), "r"(a[3]), "r"(b0), "r"(b1));
}
__device__ __forceinline__ void mma_hh(uint32_t c[2], const uint32_t a[4],
                                       uint32_t b0, uint32_t b1) {
    asm volatile(
        "mma.sync.aligned.m16n8k16.row.col.f16.f16.f16.f16 "
        "{%0,%1},{%2,%3,%4,%5},{%6,%7},{%0,%1};"
        : "+r"(c[0]), "+r"(c[1])
        : "r"(a[0]), "r"(a[1]), "r"(a[2]), "r"(a[3]), "r"(b0), "r"(b1));
}

// cp.async 128x128 f16 gmem tile -> swizzled smem tile (256 threads)
__device__ __forceinline__ void cp_tile(uint32_t dst, const __half* __restrict__ src,
                                        int tid) {
#pragma unroll
    for (int i = 0; i < 8; i++) {
        int idx = tid + i * 256;
        int row = idx >> 4, g = idx & 15;
        asm volatile("cp.async.cg.shared.global [%0], [%1], 16;"
                     :: "r"(dst + swz(row, g)),
                        "l"((const void*)(((const uint4*)src) + idx)));
    }
}
#define CP_COMMIT() asm volatile("cp.async.commit_group;" ::: "memory")
#define CP_WAIT()   asm volatile("cp.async.wait_all;" ::: "memory")
#define CP_WAIT_G(n) asm volatile("cp.async.wait_group %0;" :: "n"(n) : "memory")

// fp32 row-major 128x128 gmem -> f16 swizzled smem tile (256 threads)
__device__ __forceinline__ void load_w(char* dst, const float* __restrict__ W, int tid) {
#pragma unroll
    for (int i = 0; i < 8; i++) {
        int idx = tid + i * 256;
        int row = idx >> 4, g = idx & 15;
        const float4* p = (const float4*)(W + row * 128 + g * 8);
        float4 v0 = p[0], v1 = p[1];
        uint4 o;
        o.x = pack_h(v0.x, v0.y);  o.y = pack_h(v0.z, v0.w);
        o.z = pack_h(v1.x, v1.y);  o.w = pack_h(v1.z, v1.w);
        *(uint4*)(dst + swz(row, g)) = o;
    }
}

// B-operand ldmatrix for n-half nh (8 n8-tiles), k-block kk.
template <int BTR>
__device__ __forceinline__ void ldB(uint32_t sb, int kk, int nh, int lane,
                                    uint32_t b[4][4]) {
#pragma unroll
    for (int q = 0; q < 4; q++) {
        int idx = nh * 4 + q;
        if (!BTR) {
            ldm4(sb + swz(idx * 16 + ((lane >> 4) << 3) + (lane & 7),
                          kk * 2 + ((lane >> 3) & 1)), b[q]);
        } else {
            ldm4t(sb + swz(kk * 16 + ((lane >> 3) & 1) * 8 + (lane & 7),
                           idx * 2 + (lane >> 4)), b[q]);
        }
    }
}

// m16 x n128 x k128, A from smem, f32 accum.
template <int ATR, int BTR>
__device__ __forceinline__ void mm_s32(uint32_t sa, uint32_t sb,
                                       float acc[16][4], int lane, int mo) {
#pragma unroll
    for (int kk = 0; kk < 8; kk++) {
        uint32_t a[4];
        if (!ATR) {
            ldm4(sa + swz(mo + (lane & 15), kk * 2 + (lane >> 4)), a);
        } else {
            ldm4t(sa + swz(kk * 16 + ((lane >> 4) << 3) + (lane & 7),
                           (mo >> 3) + ((lane >> 3) & 1)), a);
        }
#pragma unroll
        for (int nh = 0; nh < 2; nh++) {
            uint32_t b[4][4];
            ldB<BTR>(sb, kk, nh, lane, b);
#pragma unroll
            for (int j = 0; j < 8; j++)
                mma_hf(acc[nh * 8 + j], a,
                       b[j >> 1][(j & 1) * 2], b[j >> 1][(j & 1) * 2 + 1]);
        }
    }
}

// m16 x n128 x k128, A from smem, f16 accum (accumulates).
template <int ATR, int BTR>
__device__ __forceinline__ void mm_s16(uint32_t sa, uint32_t sb,
                                       uint32_t acc[16][2], int lane, int mo) {
#pragma unroll
    for (int kk = 0; kk < 8; kk++) {
        uint32_t a[4];
        if (!ATR) {
            ldm4(sa + swz(mo + (lane & 15), kk * 2 + (lane >> 4)), a);
        } else {
            ldm4t(sa + swz(kk * 16 + ((lane >> 4) << 3) + (lane & 7),
                           (mo >> 3) + ((lane >> 3) & 1)), a);
        }
#pragma unroll
        for (int nh = 0; nh < 2; nh++) {
            uint32_t b[4][4];
            ldB<BTR>(sb, kk, nh, lane, b);
#pragma unroll
            for (int j = 0; j < 8; j++)
                mma_hh(acc[nh * 8 + j], a,
                       b[j >> 1][(j & 1) * 2], b[j >> 1][(j & 1) * 2 + 1]);
        }
    }
}

// A = f16 C-frags (identity), B from smem, f16 accum (accumulates).
template <int BTR>
__device__ __forceinline__ void mm_fh(const uint32_t U[16][2], uint32_t sb,
                                      uint32_t acc[16][2], int lane) {
#pragma unroll
    for (int kk = 0; kk < 8; kk++) {
        uint32_t a[4] = {U[2 * kk][0], U[2 * kk][1], U[2 * kk + 1][0], U[2 * kk + 1][1]};
#pragma unroll
        for (int nh = 0; nh < 2; nh++) {
            uint32_t b[4][4];
            ldB<BTR>(sb, kk, nh, lane, b);
#pragma unroll
            for (int j = 0; j < 8; j++)
                mma_hh(acc[nh * 8 + j], a,
                       b[j >> 1][(j & 1) * 2], b[j >> 1][(j & 1) * 2 + 1]);
        }
    }
}

__device__ __forceinline__ void zacc(float acc[16][4]) {
#pragma unroll
    for (int n = 0; n < 16; n++)
#pragma unroll
        for (int j = 0; j < 4; j++) acc[n][j] = 0.0f;
}
__device__ __forceinline__ void zacc16(uint32_t acc[16][2]) {
#pragma unroll
    for (int n = 0; n < 16; n++) { acc[n][0] = 0u; acc[n][1] = 0u; }
}

// f32 accum (scaled) -> f16 row-major gmem tile (m16 layout)
__device__ __forceinline__ void store_f16(const float acc[16][4],
                                          __half* __restrict__ dst,
                                          int lane, int mo, float scale) {
    int gq = lane >> 2, t = lane & 3;
#pragma unroll
    for (int nt = 0; nt < 16; nt++) {
        int col = nt * 8 + 2 * t;
        *(uint32_t*)(dst + (mo + gq) * 128 + col) =
            pack_h(acc[nt][0] * scale, acc[nt][1] * scale);
        *(uint32_t*)(dst + (mo + 8 + gq) * 128 + col) =
            pack_h(acc[nt][2] * scale, acc[nt][3] * scale);
    }
}

// f16 accum -> f16 row-major gmem tile (m16 layout, no conversion)
__device__ __forceinline__ void store_h16(const uint32_t acc[16][2],
                                          __half* __restrict__ dst,
                                          int lane, int mo) {
    int gq = lane >> 2, t = lane & 3;
#pragma unroll
    for (int nt = 0; nt < 16; nt++) {
        int col = nt * 8 + 2 * t;
        *(uint32_t*)(dst + (mo + gq) * 128 + col)     = acc[nt][0];
        *(uint32_t*)(dst + (mo + 8 + gq) * 128 + col) = acc[nt][1];
    }
}

// ===========================================================================
// Kernel 0: ONE prep launch (grid=2).
//   CTA0: G' = (Wq^T Wk / sqrt(H)) * 1024     CTA1: W2 = Wo @ Wv
// ===========================================================================
#define KP_SMEM (2 * 32768)

extern "C" __global__ void __launch_bounds__(256, 1)
k_prep(const float* __restrict__ Wq, const float* __restrict__ Wk,
       const float* __restrict__ Wv, const float* __restrict__ Wo) {
    extern __shared__ char smem[];
    char* a = smem;
    char* b = smem + 32768;
    int tid = threadIdx.x, wid = tid >> 5, lane = tid & 31;
    int mo = wid * 16;
    uint32_t sa = smem_u32(a), sb = smem_u32(b);
    float acc[16][4];

    if (blockIdx.x == 0) {
        load_w(a, Wq, tid);
        load_w(b, Wk, tid);
        __syncthreads();
        zacc(acc);
        mm_s32<1, 1>(sa, sb, acc, lane, mo);    // G[t1][t2] = sum_h Wq[h][t1] Wk[h][t2]
        store_f16(acc, g_G, lane, mo, RSQRT_H * PRESCALE);
    } else {
        load_w(a, Wo, tid);
        load_w(b, Wv, tid);
        __syncthreads();
        zacc(acc);
        mm_s32<0, 1>(sa, sb, acc, lane, mo);    // W2[o][t] = sum_v Wo[o][v] Wv[v][t]
        store_f16(acc, g_W2, lane, mo, 1.0f);
    }
}

// ===========================================================================
// Fused persistent kernel.  smem: b0=Tn (resident) -> proj stage /
// b1=G -> W2 / b2=Tpre.  U' and P fully register-resident.
// ===========================================================================
#define KF_SMEM (3 * 32768)

extern "C" __global__ void __launch_bounds__(256, 2)
k_fused(const float* __restrict__ tokens,
        const float* __restrict__ g1, const float* __restrict__ b1v,
        const float* __restrict__ g2, const float* __restrict__ b2v,
        float* __restrict__ out) {
    extern __shared__ char smem[];
    char* b0 = smem;
    char* b1 = smem + 32768;
    char* b2 = smem + 65536;
    int tid = threadIdx.x, wid = tid >> 5, lane = tid & 31;
    int mo = wid * 16;
    int gq = lane >> 2, t = lane & 3;
    int cid = blockIdx.x, base = cid * CH;
    int bb = cid >> 6;                      // batch index
    uint32_t sb0 = smem_u32(b0), sb1 = smem_u32(b1), sb2 = smem_u32(b2);

    // ============================ PHASE A ==================================
    cp_tile(sb1, g_G, tid);                 // G -> b1 (for U below)
    CP_COMMIT();

    for (int r = wid; r < CH; r += 8) {
        float4 v = ((const float4*)(tokens + (size_t)(base + r) * 128))[lane];
        float s  = v.x + v.y + v.z + v.w;
        float s2 = v.x * v.x + v.y * v.y + v.z * v.z + v.w * v.w;
#pragma unroll
        for (int o = 16; o; o >>= 1) {
            s  += __shfl_xor_sync(0xffffffffu, s, o);
            s2 += __shfl_xor_sync(0xffffffffu, s2, o);
        }
        float mu  = s * (1.0f / 128.0f);
        float var = fmaxf(s2 * (1.0f / 128.0f) - mu * mu, 0.0f);
        float inv = rsqrtf(var + 1e-5f);
        float4 gg = ((const float4*)g1)[lane];
        float4 bb4 = ((const float4*)b1v)[lane];
        float o0 = (v.x - mu) * inv * gg.x + bb4.x;
        float o1 = (v.y - mu) * inv * gg.y + bb4.y;
        float o2 = (v.z - mu) * inv * gg.z + bb4.z;
        float o3 = (v.w - mu) * inv * gg.w + bb4.w;
        uint32_t off = swz(r, lane >> 1) + (lane & 1) * 8;
        *(uint32_t*)(b0 + off)     = pack_h(o0, o1);
        *(uint32_t*)(b0 + off + 4) = pack_h(o2, o3);
    }
    CP_WAIT();
    __syncthreads();

    // T = Tn^T @ Tn -> g_S  (f16 accum: error impact ~3e-11 on output)
    {
        uint32_t accT[16][2];
        zacc16(accT);
        mm_s16<1, 1>(sb0, sb0, accT, lane, mo);
        store_h16(accT, g_S + (size_t)cid * TILE, lane, mo);
    }

    // U' = Tn @ G'  (f16 acc; B = G trans); lives in registers across barriers
    uint32_t Ua[16][2];
    zacc16(Ua);
    mm_s16<0, 1>(sb0, sb1, Ua, lane, mo);

    batch_bar(g_bar1, bb);                  // own batch's T all visible

    // ============================ PHASE B ==================================
    // half2 scan over OWN batch: 128 walkers/CTA, each owns one element pair.
    if (tid < 128) {
        int e = (cid * 128 + tid) & 8191;   // pair index in the batch tile
        const __half2* S = (const __half2*)(g_S + (size_t)bb * NCB * TILE) + e;
        __half2* M = (__half2*)(g_M + (size_t)bb * NCB * TILE) + e;
        float sx = 0.0f, sy = 0.0f;
#pragma unroll 8
        for (int c = 0; c < NCB; c++) {
            M[(size_t)c * (TILE / 2)] = __floats2half2_rn(sx, sy);
            float2 v = __half22float2(S[(size_t)c * (TILE / 2)]);
            sx += v.x;
            sy += v.y;
        }
    }

    batch_bar(g_bar2, bb);                  // own batch's Tpre all visible

    // ============================ PHASE C ==================================
    // Prefetch Tpre (group 1) and W2 (group 0) immediately; both overlap the
    // scores MMA below (which reads only b0).
    cp_tile(sb2, g_M + (size_t)cid * TILE, tid);
    CP_COMMIT();
    cp_tile(sb1, g_W2, tid);
    CP_COMMIT();

    // scores' = U' @ Tn^T  (f16 acc; B = Tn non-trans)
    uint32_t accS[16][2];
    zacc16(accS);
    mm_fh<0>(Ua, sb0, accS, lane);

    // causal mask IN REGISTERS -> Pf (accS in place)
    {
        __half z = __float2half(0.0f);
#pragma unroll
        for (int nt = 0; nt < 16; nt++) {
            int col = nt * 8 + 2 * t;
            int r0 = mo + gq, r1 = r0 + 8;
            __half2 h0 = *reinterpret_cast<__half2*>(&accS[nt][0]);
            __half2 h1 = *reinterpret_cast<__half2*>(&accS[nt][1]);
            if (col     > r0) h0.x = z;
            if (col + 1 > r0) h0.y = z;
            if (col     > r1) h1.x = z;
            if (col + 1 > r1) h1.y = z;
            accS[nt][0] = *reinterpret_cast<uint32_t*>(&h0);
            accS[nt][1] = *reinterpret_cast<uint32_t*>(&h1);
        }
    }

    // Z' = Pf @ Tn  (A = masked frags, B = Tn trans)
    uint32_t accZ[16][2];
    zacc16(accZ);
    mm_fh<1>(accS, sb0, accZ, lane);

    CP_WAIT_G(1);                           // Tpre landed
    __syncthreads();                        // S1: b2 readable by all warps

    // Z' += U' @ Tpre  (Tpre symmetric -> non-trans read)
    mm_fh<0>(Ua, sb2, accZ, lane);

    CP_WAIT_G(0);                           // W2 landed (long ago)
    __syncthreads();                        // S2: b1 readable; b0 reads all done

    // proj' = Z' @ W2^T  (f16 acc; A = accZ frags directly)
    uint32_t accP[16][2];
    zacc16(accP);
    mm_fh<0>(accZ, sb1, accP, lane);

    // proj' -> b0 f16 row-major (raw halves; final scale applied at LN2 read)
#pragma unroll
    for (int nt = 0; nt < 16; nt++) {
        int col = nt * 8 + 2 * t;
        int r0 = mo + gq, r1 = r0 + 8;
        *(uint32_t*)(b0 + (r0 * 128 + col) * 2) = accP[nt][0];
        *(uint32_t*)(b0 + (r1 * 128 + col) * 2) = accP[nt][1];
    }
    __syncthreads();                        // S3: proj visible

    // LN2(tokens + FINAL_SCALE * proj') -> out
    for (int r = wid; r < CH; r += 8) {
        float4 tv = ((const float4*)(tokens + (size_t)(base + r) * 128))[lane];
        uint2 pr = *(const uint2*)(b0 + (r * 128 + lane * 4) * 2);
        __half2 p0 = *reinterpret_cast<__half2*>(&pr.x);
        __half2 p1 = *reinterpret_cast<__half2*>(&pr.y);
        float x0 = tv.x + FINAL_SCALE * __half2float(p0.x);
        float x1 = tv.y + FINAL_SCALE * __half2float(p0.y);
        float x2 = tv.z + FINAL_SCALE * __half2float(p1.x);
        float x3 = tv.w + FINAL_SCALE * __half2float(p1.y);
        float s  = x0 + x1 + x2 + x3;
        float s2 = x0 * x0 + x1 * x1 + x2 * x2 + x3 * x3;
#pragma unroll
        for (int o = 16; o; o >>= 1) {
            s  += __shfl_xor_sync(0xffffffffu, s, o);
            s2 += __shfl_xor_sync(0xffffffffu, s2, o);
        }
        float mu  = s * (1.0f / 128.0f);
        float var = fmaxf(s2 * (1.0f / 128.0f) - mu * mu, 0.0f);
        float inv = rsqrtf(var + 1e-5f);
        float4 gg = ((const float4*)g2)[lane];
        float4 bb4 = ((const float4*)b2v)[lane];
        float4 o4;
        o4.x = (x0 - mu) * inv * gg.x + bb4.x;
        o4.y = (x1 - mu) * inv * gg.y + bb4.y;
        o4.z = (x2 - mu) * inv * gg.z + bb4.z;
        o4.w = (x3 - mu) * inv * gg.w + bb4.w;
        ((float4*)(out + (size_t)(base + r) * 128))[lane] = o4;
    }
}

// ===========================================================================
extern "C" void kernel_launch(void* const* d_in, const int* in_sizes, int n_in,
                              void* d_out, int out_size) {
    const float* tokens = (const float*)d_in[0];
    const float* Wq = (const float*)d_in[1];
    const float* Wk = (const float*)d_in[2];
    const float* Wv = (const float*)d_in[3];
    const float* Wo = (const float*)d_in[4];
    const float* g1 = (const float*)d_in[5];
    const float* b1 = (const float*)d_in[6];
    const float* g2 = (const float*)d_in[7];
    const float* b2 = (const float*)d_in[8];
    float* out = (float*)d_out;

    cudaFuncSetAttribute(k_prep,  cudaFuncAttributeMaxDynamicSharedMemorySize, KP_SMEM);
    cudaFuncSetAttribute(k_fused, cudaFuncAttributeMaxDynamicSharedMemorySize, KF_SMEM);

    k_prep<<<2, 256, KP_SMEM>>>(Wq, Wk, Wv, Wo);
    k_fused<<<NCHUNK, 256, KF_SMEM>>>(tokens, g1, b1, g2, b2, out);
}